// round 14
// baseline (speedup 1.0000x reference)
#include <cuda_runtime.h>
#include <cuda_bf16.h>

// Problem constants: B=32, M=32768, D=128, R=64, W=129
#define RB_B 32
#define RB_M 32768
#define RB_D 128
#define RB_W 129

// out[b,m,:] = ring[b,m,:] unless off=(m-start[b]) mod M < W:
//   w = weights[b,off]; out = ring*(1-erase[b]*w) + write_gate[b]*w*write_vec[b,:]
//
// FINAL (converged). HBM-bound copy: 512MB read + 512MB write compulsory.
// Measured sustained 6.75-6.80 TB/s (85-86% of 8TB/s spec) — invariant over
// occupancy (43-93%), MLP_p1 (1/4/8), access width (LDG.128/LDG.256), block
// size (256/512), and one-shot vs persistent scheduling => path-level
// sustained-HBM cap for balanced R+W streams, not an SM-side limit.
// Best measured configuration (R6): one-shot CTAs, 256 threads, MLP_p1=4
// front-batched LDG.128 + streaming hints, 32 regs (~8 CTA/SM).

__global__ __launch_bounds__(256) void ring_update_kernel(
    const float4* __restrict__ ring4,     // B*M*D/4 float4
    const float4* __restrict__ wvec4,     // B*D/4 float4
    const float*  __restrict__ weights,   // B*W
    const float*  __restrict__ erase,     // B
    const float*  __restrict__ wgate,     // B
    const int*    __restrict__ idx,       // B*W
    float4*       __restrict__ out4)
{
    const int D4 = RB_D / 4;  // 32

    // Block covers 4*256 = 1024 consecutive float4s (= 32 full rows),
    // always fully inside one batch (per-batch 2^20 float4 is a multiple).
    int g = blockIdx.x * 1024 + threadIdx.x;

    int    vec[4];
    float4 cur[4];

    // Front-batched independent loads: MLP_p1 = 4, streaming (no reuse).
#pragma unroll
    for (int k = 0; k < 4; k++) {
        vec[k] = g + k * 256;
        cur[k] = __ldcs(&ring4[vec[k]]);
    }

#pragma unroll
    for (int k = 0; k < 4; k++) {
        int v   = vec[k];
        int d4  = v & (D4 - 1);        // v % 32
        int row = v >> 5;              // b*M + m
        int m   = row & (RB_M - 1);
        int b   = row >> 15;

        int start = __ldg(&idx[b * RB_W]);      // broadcast, L1-resident
        int off   = (m - start) & (RB_M - 1);

        if (off < RB_W) {
            float w  = __ldg(&weights[b * RB_W + off]);
            float e  = __ldg(&erase[b]);
            float gt = __ldg(&wgate[b]);
            float keep = 1.0f - e * w;
            float add  = gt * w;
            float4 wv = __ldg(&wvec4[b * D4 + d4]);
            cur[k].x = cur[k].x * keep + add * wv.x;
            cur[k].y = cur[k].y * keep + add * wv.y;
            cur[k].z = cur[k].z * keep + add * wv.z;
            cur[k].w = cur[k].w * keep + add * wv.w;
        }
    }

#pragma unroll
    for (int k = 0; k < 4; k++) {
        __stcs(&out4[vec[k]], cur[k]);
    }
}

extern "C" void kernel_launch(void* const* d_in, const int* in_sizes, int n_in,
                              void* d_out, int out_size)
{
    const float4* ring4   = (const float4*)d_in[0];
    const float4* wvec4   = (const float4*)d_in[1];
    const float*  weights = (const float*)d_in[2];
    const float*  erase   = (const float*)d_in[3];
    const float*  wgate   = (const float*)d_in[4];
    const int*    idx     = (const int*)d_in[5];
    float4*       out4    = (float4*)d_out;

    const long long total = (long long)RB_B * RB_M * (RB_D / 4);   // 2^25 float4
    const int threads = 256;
    const int per_block = threads * 4;                              // 1024 float4
    const int blocks = (int)(total / per_block);                    // 32768 (exact)

    ring_update_kernel<<<blocks, threads>>>(ring4, wvec4, weights, erase, wgate, idx, out4);
}

// round 15
// speedup vs baseline: 1.0111x; 1.0111x over previous
#include <cuda_runtime.h>
#include <cuda_bf16.h>

// Problem constants: B=32, M=32768, D=128, R=64, W=129
#define RB_B 32
#define RB_M 32768
#define RB_D 128
#define RB_W 129

// out[b,m,:] = ring[b,m,:] unless off=(m-start[b]) mod M < W:
//   w = weights[b,off]; out = ring*(1-erase[b]*w) + write_gate[b]*w*write_vec[b,:]
//
// FINAL (converged, frozen). HBM-bound copy: 512MB read + 512MB write
// compulsory. Sustained 6.65-6.80 TB/s (83-86% of spec) measured invariant
// over occupancy (43-93%), MLP_p1 (1/4/8), LDG.128 vs LDG.256, block size
// (256/512), one-shot vs persistent => path-level sustained-HBM cap for
// balanced R+W streams; no SM-side lever remains with predicted win > noise.
// Best measured configuration (R6, 157.06us wall): one-shot CTAs, 256
// threads, MLP_p1=4 front-batched LDG.128 + streaming hints, 32 regs.

__global__ __launch_bounds__(256) void ring_update_kernel(
    const float4* __restrict__ ring4,     // B*M*D/4 float4
    const float4* __restrict__ wvec4,     // B*D/4 float4
    const float*  __restrict__ weights,   // B*W
    const float*  __restrict__ erase,     // B
    const float*  __restrict__ wgate,     // B
    const int*    __restrict__ idx,       // B*W
    float4*       __restrict__ out4)
{
    const int D4 = RB_D / 4;  // 32

    // Block covers 4*256 = 1024 consecutive float4s (= 32 full rows),
    // always fully inside one batch (per-batch 2^20 float4 is a multiple).
    int g = blockIdx.x * 1024 + threadIdx.x;

    int    vec[4];
    float4 cur[4];

    // Front-batched independent loads: MLP_p1 = 4, streaming (no reuse).
#pragma unroll
    for (int k = 0; k < 4; k++) {
        vec[k] = g + k * 256;
        cur[k] = __ldcs(&ring4[vec[k]]);
    }

#pragma unroll
    for (int k = 0; k < 4; k++) {
        int v   = vec[k];
        int d4  = v & (D4 - 1);        // v % 32
        int row = v >> 5;              // b*M + m
        int m   = row & (RB_M - 1);
        int b   = row >> 15;

        int start = __ldg(&idx[b * RB_W]);      // broadcast, L1-resident
        int off   = (m - start) & (RB_M - 1);

        if (off < RB_W) {
            float w  = __ldg(&weights[b * RB_W + off]);
            float e  = __ldg(&erase[b]);
            float gt = __ldg(&wgate[b]);
            float keep = 1.0f - e * w;
            float add  = gt * w;
            float4 wv = __ldg(&wvec4[b * D4 + d4]);
            cur[k].x = cur[k].x * keep + add * wv.x;
            cur[k].y = cur[k].y * keep + add * wv.y;
            cur[k].z = cur[k].z * keep + add * wv.z;
            cur[k].w = cur[k].w * keep + add * wv.w;
        }
    }

#pragma unroll
    for (int k = 0; k < 4; k++) {
        __stcs(&out4[vec[k]], cur[k]);
    }
}

extern "C" void kernel_launch(void* const* d_in, const int* in_sizes, int n_in,
                              void* d_out, int out_size)
{
    const float4* ring4   = (const float4*)d_in[0];
    const float4* wvec4   = (const float4*)d_in[1];
    const float*  weights = (const float*)d_in[2];
    const float*  erase   = (const float*)d_in[3];
    const float*  wgate   = (const float*)d_in[4];
    const int*    idx     = (const int*)d_in[5];
    float4*       out4    = (float4*)d_out;

    const long long total = (long long)RB_B * RB_M * (RB_D / 4);   // 2^25 float4
    const int threads = 256;
    const int per_block = threads * 4;                              // 1024 float4
    const int blocks = (int)(total / per_block);                    // 32768 (exact)

    ring_update_kernel<<<blocks, threads>>>(ring4, wvec4, weights, erase, wgate, idx, out4);
}